// round 15
// baseline (speedup 1.0000x reference)
#include <cuda_runtime.h>
#include <cuda_fp16.h>
#include <cstdint>

#define Bn 16
#define Cn 512
#define Tn 1024
#define NHn 8
#define Dn 64

// Scratch (device globals: no allocations allowed)
__device__ __half g_xn16[Bn * Cn * Tn];   // group-normed input, fp16 [b][c][t]
__device__ __half g_q[Bn * Cn * Tn];      // [b][h][d][t], PRE-SCALED by SC
__device__ __half g_k[Bn * Cn * Tn];
__device__ __half g_v[Bn * Cn * Tn];
__device__ __half g_a16[Bn * Cn * Tn];    // attention output fp16 [b][c][t]
__device__ __half g_wq16[3 * Cn * Cn];    // qkv weights fp16 [1536][512]
__device__ __half g_wp16[Cn * Cn];        // proj weights fp16 [512][512]

#define SCf (0.125f * 1.4426950408889634f)   // 0.125 * log2(e)

// ---------------------------------------------------------------------------
// Helpers
// ---------------------------------------------------------------------------
__device__ __forceinline__ uint32_t cvta_s(const void* p) {
    return (uint32_t)__cvta_generic_to_shared(p);
}
// swizzle for 128-byte rows (XOR 16B-chunk bits[4:6] with row bits[7:9])
__device__ __forceinline__ int S128s(int x) { return x ^ ((x >> 3) & 0x70); }
// swizzle for 256-byte rows (XOR chunk bits[4:6] with row bits[8:10])
__device__ __forceinline__ int S256s(int x) { return x ^ ((x >> 4) & 0x70); }

__device__ __forceinline__ void ldmA(uint32_t (&r)[4], uint32_t a) {
    asm volatile("ldmatrix.sync.aligned.m8n8.x4.shared.b16 {%0,%1,%2,%3}, [%4];"
        : "=r"(r[0]), "=r"(r[1]), "=r"(r[2]), "=r"(r[3]) : "r"(a));
}
__device__ __forceinline__ void ldmA_t(uint32_t (&r)[4], uint32_t a) {
    asm volatile("ldmatrix.sync.aligned.m8n8.x4.trans.shared.b16 {%0,%1,%2,%3}, [%4];"
        : "=r"(r[0]), "=r"(r[1]), "=r"(r[2]), "=r"(r[3]) : "r"(a));
}
__device__ __forceinline__ void mma2(float (&c)[4], const uint32_t (&a)[4],
                                     uint32_t b0, uint32_t b1) {
    asm volatile("mma.sync.aligned.m16n8k16.row.col.f32.f16.f16.f32 "
        "{%0,%1,%2,%3}, {%4,%5,%6,%7}, {%8,%9}, {%0,%1,%2,%3};"
        : "+f"(c[0]), "+f"(c[1]), "+f"(c[2]), "+f"(c[3])
        : "r"(a[0]), "r"(a[1]), "r"(a[2]), "r"(a[3]), "r"(b0), "r"(b1));
}
__device__ __forceinline__ uint32_t hexp2pack(float a, float b) {
    __half2 h = h2exp2(__floats2half2_rn(a, b));
    return *reinterpret_cast<uint32_t*>(&h);
}
__device__ __forceinline__ float hsum2f(uint32_t u) {
    float2 f = __half22float2(*reinterpret_cast<__half2*>(&u));
    return f.x + f.y;
}
__device__ __forceinline__ void cpa16(uint32_t dst, const void* src) {
    asm volatile("cp.async.cg.shared.global [%0], [%1], 16;" :: "r"(dst), "l"(src));
}
#define CP_COMMIT() asm volatile("cp.async.commit_group;" ::: "memory")
#define CP_WAIT1()  asm volatile("cp.async.wait_group 1;" ::: "memory")

// ---------------------------------------------------------------------------
// Kernel 0: convert weights fp32 -> fp16 (vectorized)
// ---------------------------------------------------------------------------
__global__ __launch_bounds__(256) void conv_w(const float* __restrict__ qw,
                                              const float* __restrict__ pw)
{
    int i = blockIdx.x * 256 + threadIdx.x;   // element-group of 4
    if (i < 3 * Cn * Cn / 4) {
        float4 v = *(const float4*)(qw + i * 4);
        __half2 h0 = __floats2half2_rn(v.x, v.y);
        __half2 h1 = __floats2half2_rn(v.z, v.w);
        uint2 u; u.x = *(uint32_t*)&h0; u.y = *(uint32_t*)&h1;
        *(uint2*)(g_wq16 + i * 4) = u;
    }
    if (i < Cn * Cn / 4) {
        float4 v = *(const float4*)(pw + i * 4);
        __half2 h0 = __floats2half2_rn(v.x, v.y);
        __half2 h1 = __floats2half2_rn(v.z, v.w);
        uint2 u; u.x = *(uint32_t*)&h0; u.y = *(uint32_t*)&h1;
        *(uint2*)(g_wp16 + i * 4) = u;
    }
}

// ---------------------------------------------------------------------------
// Kernel 1: GroupNorm -> fp16. One block per (batch, group).
// ---------------------------------------------------------------------------
__global__ __launch_bounds__(256) void gn_kernel(
    const float* __restrict__ x, const float* __restrict__ sc,
    const float* __restrict__ bi)
{
    int bg = blockIdx.x;
    int b = bg >> 5;
    int g = bg & 31;
    int base = (b * Cn + g * 16) * Tn;
    const int NELEM = 16 * Tn;

    float s = 0.f, ss = 0.f;
    for (int i = threadIdx.x; i < NELEM / 4; i += 256) {
        float4 v = *(const float4*)(x + base + i * 4);
        s += v.x + v.y + v.z + v.w;
        ss += v.x * v.x + v.y * v.y + v.z * v.z + v.w * v.w;
    }
    #pragma unroll
    for (int o = 16; o; o >>= 1) {
        s  += __shfl_xor_sync(0xffffffffu, s,  o);
        ss += __shfl_xor_sync(0xffffffffu, ss, o);
    }
    __shared__ float rs[8], rss[8], stats[2];
    int warp = threadIdx.x >> 5, lane = threadIdx.x & 31;
    if (lane == 0) { rs[warp] = s; rss[warp] = ss; }
    __syncthreads();
    if (threadIdx.x == 0) {
        float S = 0.f, SS = 0.f;
        #pragma unroll
        for (int w = 0; w < 8; w++) { S += rs[w]; SS += rss[w]; }
        float mean = S / (float)NELEM;
        float var  = SS / (float)NELEM - mean * mean;
        stats[0] = mean;
        stats[1] = rsqrtf(var + 1e-5f);
    }
    __syncthreads();
    float mean = stats[0], inv = stats[1];
    for (int i = threadIdx.x; i < NELEM / 4; i += 256) {
        int c = g * 16 + (i >> 8);      // i*4 >> 10
        float a = inv * sc[c], bb = bi[c] - mean * a;
        float4 v = *(const float4*)(x + base + i * 4);
        __half2 h0 = __floats2half2_rn(v.x * a + bb, v.y * a + bb);
        __half2 h1 = __floats2half2_rn(v.z * a + bb, v.w * a + bb);
        uint2 u; u.x = *(uint32_t*)&h0; u.y = *(uint32_t*)&h1;
        *(uint2*)(g_xn16 + base + i * 4) = u;
    }
}

// ---------------------------------------------------------------------------
// HMMA GEMM mainloop, cp.async 3-stage ring, ONE sync per K-step,
// prefetch issued AFTER compute (off the post-barrier critical path).
// Block tile 128x128, K-step 64. Dynamic smem: 3 x (A 16KB + B 16KB) = 96KB.
// 256 threads = 8 warps (2 m x 4 n), warp tile 64x32.
// ---------------------------------------------------------------------------
__device__ __forceinline__ void hgemm_issue(
    const __half* __restrict__ Ag, const __half* __restrict__ Bg,
    char* slot, int o0, int t0, int c0, int tid)
{
    uint32_t sA = cvta_s(slot);
    uint32_t sB = sA + 16384;
    #pragma unroll
    for (int r = 0; r < 4; r++) {
        int id = tid + r * 256;
        int m = id >> 3, ch = id & 7;
        cpa16(sA + S128s(m * 128 + ch * 16), Ag + (o0 + m) * Cn + c0 + ch * 8);
    }
    #pragma unroll
    for (int r = 0; r < 4; r++) {
        int id = tid + r * 256;
        int k = id >> 4, ch = id & 15;
        cpa16(sB + S256s(k * 256 + ch * 16), Bg + (c0 + k) * Tn + t0 + ch * 8);
    }
}

__device__ __forceinline__ void hgemm_compute(
    char* slot, float (&acc)[4][4][4], int lane, int wm, int wn)
{
    uint32_t sA = cvta_s(slot);
    uint32_t sB = sA + 16384;
    #pragma unroll
    for (int kk = 0; kk < 4; kk++) {
        uint32_t a[4][4];
        #pragma unroll
        for (int am = 0; am < 4; am++) {
            int row = wm * 64 + am * 16 + (lane & 15);
            int colh = kk * 16 + (lane >> 4) * 8;
            ldmA(a[am], sA + S128s(row * 128 + colh * 2));
        }
        uint32_t bfr[2][4];
        int krow = kk * 16 + (lane & 15);
        int noff = (lane >> 4) * 8;
        #pragma unroll
        for (int p = 0; p < 2; p++)
            ldmA_t(bfr[p], sB + S256s(krow * 256 + (wn * 32 + p * 16 + noff) * 2));
        #pragma unroll
        for (int am = 0; am < 4; am++)
            #pragma unroll
            for (int p = 0; p < 2; p++) {
                mma2(acc[am][2 * p],     a[am], bfr[p][0], bfr[p][1]);
                mma2(acc[am][2 * p + 1], a[am], bfr[p][2], bfr[p][3]);
            }
    }
}

__device__ __forceinline__ void hgemm_main(
    const __half* __restrict__ Ag, const __half* __restrict__ Bg,
    char* smem, float (&acc)[4][4][4], int o0, int t0)
{
    int tid = threadIdx.x;
    int lane = tid & 31, warp = tid >> 5;
    int wm = warp >> 2, wn = warp & 3;

    hgemm_issue(Ag, Bg, smem,         o0, t0, 0,  tid); CP_COMMIT();
    hgemm_issue(Ag, Bg, smem + 32768, o0, t0, 64, tid); CP_COMMIT();

    #pragma unroll 1
    for (int s = 0; s < 8; s++) {
        CP_WAIT1();
        __syncthreads();
        hgemm_compute(smem + (s % 3) * 32768, acc, lane, wm, wn);
        // slot (s+2)%3 == (s-1)%3: its readers all passed this iter's barrier
        if (s + 2 < 8)
            hgemm_issue(Ag, Bg, smem + ((s + 2) % 3) * 32768, o0, t0,
                        (s + 2) * 64, tid);
        CP_COMMIT();
    }
}

// ---------------------------------------------------------------------------
// Kernel 2: QKV GEMM (fp16 TC). Epilogue: +bias, cast fp16, scatter q/k/v.
// q is pre-scaled by SC so attention scores come out in exp2 domain.
// ---------------------------------------------------------------------------
__global__ __launch_bounds__(256, 2) void qkv_hgemm(const float* __restrict__ bias)
{
    extern __shared__ char dsm[];
    int t0 = blockIdx.x * 128, o0 = blockIdx.y * 128, b = blockIdx.z;
    float acc[4][4][4] = {};
    hgemm_main(g_wq16, g_xn16 + b * Cn * Tn, dsm, acc, o0, t0);

    int lane = threadIdx.x & 31, warp = threadIdx.x >> 5;
    int wm = warp >> 2, wn = warp & 3;
    int sel = o0 >> 9;   // whole 128-row tile lies in one of q/k/v
    __half* dst = sel == 0 ? g_q : (sel == 1 ? g_k : g_v);
    float mul = sel == 0 ? SCf : 1.0f;
    #pragma unroll
    for (int am = 0; am < 4; am++) {
        #pragma unroll
        for (int hh = 0; hh < 2; hh++) {
            int orow = o0 + wm * 64 + am * 16 + (lane >> 2) + hh * 8;
            float bv = __ldg(&bias[orow]);
            int rem = orow & 511;
            int base = (b * Cn + rem) * Tn + t0 + wn * 32 + (lane & 3) * 2;
            #pragma unroll
            for (int bn = 0; bn < 4; bn++) {
                float x0 = (acc[am][bn][hh * 2 + 0] + bv) * mul;
                float x1 = (acc[am][bn][hh * 2 + 1] + bv) * mul;
                __half2 h = __floats2half2_rn(x0, x1);
                *(__half2*)(dst + base + bn * 8) = h;
            }
        }
    }
}

// ---------------------------------------------------------------------------
// Kernel 4: Proj GEMM (fp16 TC). Epilogue: +bias +residual, fp32 out.
// ---------------------------------------------------------------------------
__global__ __launch_bounds__(256, 2) void proj_hgemm(
    const float* __restrict__ bias, const float* __restrict__ x,
    float* __restrict__ out)
{
    extern __shared__ char dsm[];
    int t0 = blockIdx.x * 128, o0 = blockIdx.y * 128, b = blockIdx.z;
    float acc[4][4][4] = {};
    hgemm_main(g_wp16, g_a16 + b * Cn * Tn, dsm, acc, o0, t0);

    int lane = threadIdx.x & 31, warp = threadIdx.x >> 5;
    int wm = warp >> 2, wn = warp & 3;
    #pragma unroll
    for (int am = 0; am < 4; am++) {
        #pragma unroll
        for (int hh = 0; hh < 2; hh++) {
            int orow = o0 + wm * 64 + am * 16 + (lane >> 2) + hh * 8;
            float bv = __ldg(&bias[orow]);
            int base = (b * Cn + orow) * Tn + t0 + wn * 32 + (lane & 3) * 2;
            #pragma unroll
            for (int bn = 0; bn < 4; bn++) {
                float2 xr = *(const float2*)(x + base + bn * 8);
                float2 o2;
                o2.x = xr.x + acc[am][bn][hh * 2 + 0] + bv;
                o2.y = xr.y + acc[am][bn][hh * 2 + 1] + bv;
                *(float2*)(out + base + bn * 8) = o2;
            }
        }
    }
}

// ---------------------------------------------------------------------------
// Kernel 3: Flash attention (fp16 TC), FAT-WARP (R13 structure) with the
// rowsum moved OFF the tensor pipe: l is accumulated as fp32 scalars from
// the packed P fragments (fma pipe, 10% busy) instead of all-ones mmas
// (tensor pipe, 66% busy — the binding pipe). Cross-lane quad reduction of
// l happens ONCE at the end (m=0 softmax: partials just add).
// 128 threads = 4 warps; each warp owns 32 query rows (two 16-row A-sets);
// every K/V B-fragment feeds TWO mmas. 3-slot K/V ring, one sync/iter,
// prefetch after compute. Dynamic smem: Q 16KB + 3 x 16KB = 64KB; 2 CTAs/SM.
// ---------------------------------------------------------------------------
__device__ __forceinline__ void issue_kv4(const __half* kb, const __half* vb,
                                          int s0, __half* Ks, int tid)
{
    uint32_t sK = cvta_s(Ks);
    #pragma unroll
    for (int r = 0; r < 4; r++) {
        int id = tid + r * 128;
        int d = id >> 3, ch = id & 7;
        uint32_t off = S128s(d * 128 + ch * 16);
        cpa16(sK + off,        kb + d * Tn + s0 + ch * 8);
        cpa16(sK + 8192 + off, vb + d * Tn + s0 + ch * 8);
    }
}

__global__ __launch_bounds__(128) void attn_h()
{
    extern __shared__ __half smemAll[];       // Q | slot0 | slot1 | slot2
    __half* Qs = smemAll;
    __half* ring = smemAll + 8192;            // 3 slots of 8192 halfs (16KB)

    int t0 = blockIdx.x * 128;
    int bh = blockIdx.z * NHn + blockIdx.y;
    const __half* qb = g_q + bh * Dn * Tn;
    const __half* kb = g_k + bh * Dn * Tn;
    const __half* vb = g_v + bh * Dn * Tn;

    int tid = threadIdx.x, lane = tid & 31, warp = tid >> 5;
    uint32_t sQ = cvta_s(Qs);

    // prologue: async-load K/V tiles 0 and 1 into slots 0 and 1
    issue_kv4(kb, vb, 0, ring, tid);
    CP_COMMIT();
    issue_kv4(kb, vb, 64, ring + 8192, tid);
    CP_COMMIT();

    // load Q tile [d][t0..t0+127] (regular loads, overlap with cp.async)
    #pragma unroll
    for (int r = 0; r < 8; r++) {
        int id = tid + r * 128;
        int d = id >> 4, ch = id & 15;
        uint4 v = *(const uint4*)(qb + d * Tn + t0 + ch * 8);
        *(uint4*)((char*)Qs + S256s(d * 256 + ch * 16)) = v;
    }
    __syncthreads();

    // Q A-frags: warp owns rows [warp*32, warp*32+32): two 16-row sets
    uint32_t qa0[4][4], qa1[4][4];
    {
        int grp = lane >> 3, rr = lane & 7;
        #pragma unroll
        for (int kk = 0; kk < 4; kk++) {
            int drow = kk * 16 + rr + (grp >> 1) * 8;
            int tc0 = warp * 32 + (grp & 1) * 8;
            ldmA_t(qa0[kk], sQ + S256s(drow * 256 + tc0 * 2));
            ldmA_t(qa1[kk], sQ + S256s(drow * 256 + (tc0 + 16) * 2));
        }
    }

    float o0[8][4] = {}, o1[8][4] = {};
    float lp00 = 0.f, lp01 = 0.f, lp10 = 0.f, lp11 = 0.f;  // per-thread l partials

    #pragma unroll 1
    for (int it = 0; it < 16; it++) {
        CP_WAIT1();
        __syncthreads();

        uint32_t sK = cvta_s(ring + (it % 3) * 8192);
        uint32_t sV = sK + 8192;

        // S = Q^T K for both row-sets; each B-frag used twice
        float sf0[8][4], sf1[8][4];
        #pragma unroll
        for (int jn = 0; jn < 8; jn++)
            #pragma unroll
            for (int c = 0; c < 4; c++) { sf0[jn][c] = 0.f; sf1[jn][c] = 0.f; }
        #pragma unroll
        for (int kk = 0; kk < 4; kk++) {
            uint32_t bf[4][4];
            int krow = kk * 16 + (lane & 15);
            int noff = (lane >> 4) * 8;
            #pragma unroll
            for (int p = 0; p < 4; p++)
                ldmA_t(bf[p], sK + S128s(krow * 128 + (p * 16 + noff) * 2));
            #pragma unroll
            for (int p = 0; p < 4; p++) {
                mma2(sf0[2 * p],     qa0[kk], bf[p][0], bf[p][1]);
                mma2(sf0[2 * p + 1], qa0[kk], bf[p][2], bf[p][3]);
                mma2(sf1[2 * p],     qa1[kk], bf[p][0], bf[p][1]);
                mma2(sf1[2 * p + 1], qa1[kk], bf[p][2], bf[p][3]);
            }
        }

        // P = exp2(S): pack + h2exp2; result IS the PV A-fragment layout.
        // l partials accumulate in fp32 on the fma pipe (frees 8 mmas/iter).
        uint32_t pa0[4][4], pa1[4][4];
        #pragma unroll
        for (int jj = 0; jj < 4; jj++) {
            pa0[jj][0] = hexp2pack(sf0[2 * jj][0],     sf0[2 * jj][1]);
            pa0[jj][1] = hexp2pack(sf0[2 * jj][2],     sf0[2 * jj][3]);
            pa0[jj][2] = hexp2pack(sf0[2 * jj + 1][0], sf0[2 * jj + 1][1]);
            pa0[jj][3] = hexp2pack(sf0[2 * jj + 1][2], sf0[2 * jj + 1][3]);
            pa1[jj][0] = hexp2pack(sf1[2 * jj][0],     sf1[2 * jj][1]);
            pa1[jj][1] = hexp2pack(sf1[2 * jj][2],     sf1[2 * jj][3]);
            pa1[jj][2] = hexp2pack(sf1[2 * jj + 1][0], sf1[2 * jj + 1][1]);
            pa1[jj][3] = hexp2pack(sf1[2 * jj + 1][2], sf1[2 * jj + 1][3]);
            lp00 += hsum2f(pa0[jj][0]) + hsum2f(pa0[jj][2]);
            lp01 += hsum2f(pa0[jj][1]) + hsum2f(pa0[jj][3]);
            lp10 += hsum2f(pa1[jj][0]) + hsum2f(pa1[jj][2]);
            lp11 += hsum2f(pa1[jj][1]) + hsum2f(pa1[jj][3]);
        }

        // O += P V; each V B-frag used twice.
        #pragma unroll
        for (int jj = 0; jj < 4; jj++) {
            uint32_t bf[4][4];
            int scol = jj * 16 + ((lane >> 3) & 1) * 8;
            #pragma unroll
            for (int p = 0; p < 4; p++) {
                int drow = (2 * p + (lane >> 4)) * 8 + (lane & 7);
                ldmA(bf[p], sV + S128s(drow * 128 + scol * 2));
            }
            #pragma unroll
            for (int p = 0; p < 4; p++) {
                mma2(o0[2 * p],     pa0[jj], bf[p][0], bf[p][1]);
                mma2(o0[2 * p + 1], pa0[jj], bf[p][2], bf[p][3]);
                mma2(o1[2 * p],     pa1[jj], bf[p][0], bf[p][1]);
                mma2(o1[2 * p + 1], pa1[jj], bf[p][2], bf[p][3]);
            }
        }

        // prefetch tile it+2 into slot (it+2)%3 == (it-1)%3
        if (it + 2 < 16)
            issue_kv4(kb, vb, it * 64 + 128, ring + ((it + 2) % 3) * 8192, tid);
        CP_COMMIT();
    }

    // finish l: reduce per-thread partials across the 4 lanes of each quad
    // (lanes of a quad hold different columns of the same rows).
    lp00 += __shfl_xor_sync(0xffffffffu, lp00, 1);
    lp00 += __shfl_xor_sync(0xffffffffu, lp00, 2);
    lp01 += __shfl_xor_sync(0xffffffffu, lp01, 1);
    lp01 += __shfl_xor_sync(0xffffffffu, lp01, 2);
    lp10 += __shfl_xor_sync(0xffffffffu, lp10, 1);
    lp10 += __shfl_xor_sync(0xffffffffu, lp10, 2);
    lp11 += __shfl_xor_sync(0xffffffffu, lp11, 1);
    lp11 += __shfl_xor_sync(0xffffffffu, lp11, 2);

    // epilogue: normalize, stage [d][t] in Q buffer, copy out
    __syncthreads();
    float i00 = 1.f / lp00, i01 = 1.f / lp01;
    float i10 = 1.f / lp10, i11 = 1.f / lp11;
    #pragma unroll
    for (int jn = 0; jn < 8; jn++) {
        int d = jn * 8 + (lane & 3) * 2;
        int tl = warp * 32 + (lane >> 2);
        *(__half*)((char*)Qs + S256s( d      * 256 +  tl       * 2)) = __float2half(o0[jn][0] * i00);
        *(__half*)((char*)Qs + S256s((d + 1) * 256 +  tl       * 2)) = __float2half(o0[jn][1] * i00);
        *(__half*)((char*)Qs + S256s( d      * 256 + (tl + 8)  * 2)) = __float2half(o0[jn][2] * i01);
        *(__half*)((char*)Qs + S256s((d + 1) * 256 + (tl + 8)  * 2)) = __float2half(o0[jn][3] * i01);
        *(__half*)((char*)Qs + S256s( d      * 256 + (tl + 16) * 2)) = __float2half(o1[jn][0] * i10);
        *(__half*)((char*)Qs + S256s((d + 1) * 256 + (tl + 16) * 2)) = __float2half(o1[jn][1] * i10);
        *(__half*)((char*)Qs + S256s( d      * 256 + (tl + 24) * 2)) = __float2half(o1[jn][2] * i11);
        *(__half*)((char*)Qs + S256s((d + 1) * 256 + (tl + 24) * 2)) = __float2half(o1[jn][3] * i11);
    }
    __syncthreads();
    #pragma unroll
    for (int r = 0; r < 8; r++) {
        int id = tid + r * 128;
        int d = id >> 4, ch = id & 15;
        uint4 v = *(const uint4*)((char*)Qs + S256s(d * 256 + ch * 16));
        *(uint4*)(g_a16 + (bh * Dn + d) * Tn + t0 + ch * 8) = v;
    }
}

// ---------------------------------------------------------------------------
extern "C" void kernel_launch(void* const* d_in, const int* in_sizes, int n_in,
                              void* d_out, int out_size)
{
    (void)in_sizes; (void)n_in; (void)out_size;
    const float* x        = (const float*)d_in[0];
    const float* gn_scale = (const float*)d_in[1];
    const float* gn_bias  = (const float*)d_in[2];
    const float* qkv_w    = (const float*)d_in[3];
    const float* qkv_b    = (const float*)d_in[4];
    const float* proj_w   = (const float*)d_in[5];
    const float* proj_b   = (const float*)d_in[6];
    float* out = (float*)d_out;

    static bool attr_done = false;
    if (!attr_done) {
        cudaFuncSetAttribute(qkv_hgemm,
            cudaFuncAttributeMaxDynamicSharedMemorySize, 98304);
        cudaFuncSetAttribute(proj_hgemm,
            cudaFuncAttributeMaxDynamicSharedMemorySize, 98304);
        cudaFuncSetAttribute(attn_h,
            cudaFuncAttributeMaxDynamicSharedMemorySize, 65536);
        attr_done = true;
    }

    conv_w<<<(3 * Cn * Cn / 4 + 255) / 256, 256>>>(qkv_w, proj_w);
    gn_kernel<<<Bn * 32, 256>>>(x, gn_scale, gn_bias);
    qkv_hgemm<<<dim3(Tn / 128, (3 * Cn) / 128, Bn), 256, 98304>>>(qkv_b);
    attn_h<<<dim3(Tn / 128, NHn, Bn), 128, 65536>>>();
    proj_hgemm<<<dim3(Tn / 128, Cn / 128, Bn), 256, 98304>>>(proj_b, x, out);
}

// round 16
// speedup vs baseline: 1.0667x; 1.0667x over previous
#include <cuda_runtime.h>
#include <cuda_fp16.h>
#include <cstdint>

#define Bn 16
#define Cn 512
#define Tn 1024
#define NHn 8
#define Dn 64

// Scratch (device globals: no allocations allowed)
__device__ __half g_xn16[Bn * Cn * Tn];   // group-normed input, fp16 [b][c][t]
__device__ __half g_q[Bn * Cn * Tn];      // [b][h][d][t], PRE-SCALED by SC
__device__ __half g_k[Bn * Cn * Tn];
__device__ __half g_v[Bn * Cn * Tn];
__device__ __half g_a16[Bn * Cn * Tn];    // attention output fp16 [b][c][t]
__device__ __half g_wq16[3 * Cn * Cn];    // qkv weights fp16 [1536][512]
__device__ __half g_wp16[Cn * Cn];        // proj weights fp16 [512][512]

#define SCf (0.125f * 1.4426950408889634f)   // 0.125 * log2(e)

// ---------------------------------------------------------------------------
// Helpers
// ---------------------------------------------------------------------------
__device__ __forceinline__ uint32_t cvta_s(const void* p) {
    return (uint32_t)__cvta_generic_to_shared(p);
}
// swizzle for 128-byte rows (XOR 16B-chunk bits[4:6] with row bits[7:9])
__device__ __forceinline__ int S128s(int x) { return x ^ ((x >> 3) & 0x70); }
// swizzle for 256-byte rows (XOR chunk bits[4:6] with row bits[8:10])
__device__ __forceinline__ int S256s(int x) { return x ^ ((x >> 4) & 0x70); }

__device__ __forceinline__ void ldmA(uint32_t (&r)[4], uint32_t a) {
    asm volatile("ldmatrix.sync.aligned.m8n8.x4.shared.b16 {%0,%1,%2,%3}, [%4];"
        : "=r"(r[0]), "=r"(r[1]), "=r"(r[2]), "=r"(r[3]) : "r"(a));
}
__device__ __forceinline__ void ldmA_t(uint32_t (&r)[4], uint32_t a) {
    asm volatile("ldmatrix.sync.aligned.m8n8.x4.trans.shared.b16 {%0,%1,%2,%3}, [%4];"
        : "=r"(r[0]), "=r"(r[1]), "=r"(r[2]), "=r"(r[3]) : "r"(a));
}
__device__ __forceinline__ void mma2(float (&c)[4], const uint32_t (&a)[4],
                                     uint32_t b0, uint32_t b1) {
    asm volatile("mma.sync.aligned.m16n8k16.row.col.f32.f16.f16.f32 "
        "{%0,%1,%2,%3}, {%4,%5,%6,%7}, {%8,%9}, {%0,%1,%2,%3};"
        : "+f"(c[0]), "+f"(c[1]), "+f"(c[2]), "+f"(c[3])
        : "r"(a[0]), "r"(a[1]), "r"(a[2]), "r"(a[3]), "r"(b0), "r"(b1));
}
__device__ __forceinline__ uint32_t hexp2pack(float a, float b) {
    __half2 h = h2exp2(__floats2half2_rn(a, b));
    return *reinterpret_cast<uint32_t*>(&h);
}
__device__ __forceinline__ uint32_t hadd2u(uint32_t a, uint32_t b) {
    __half2 r = __hadd2(*reinterpret_cast<__half2*>(&a),
                        *reinterpret_cast<__half2*>(&b));
    return *reinterpret_cast<uint32_t*>(&r);
}
__device__ __forceinline__ void cpa16(uint32_t dst, const void* src) {
    asm volatile("cp.async.cg.shared.global [%0], [%1], 16;" :: "r"(dst), "l"(src));
}
#define CP_COMMIT() asm volatile("cp.async.commit_group;" ::: "memory")
#define CP_WAIT1()  asm volatile("cp.async.wait_group 1;" ::: "memory")

// ---------------------------------------------------------------------------
// Kernel 0: convert weights fp32 -> fp16 (vectorized)
// ---------------------------------------------------------------------------
__global__ __launch_bounds__(256) void conv_w(const float* __restrict__ qw,
                                              const float* __restrict__ pw)
{
    int i = blockIdx.x * 256 + threadIdx.x;   // element-group of 4
    if (i < 3 * Cn * Cn / 4) {
        float4 v = *(const float4*)(qw + i * 4);
        __half2 h0 = __floats2half2_rn(v.x, v.y);
        __half2 h1 = __floats2half2_rn(v.z, v.w);
        uint2 u; u.x = *(uint32_t*)&h0; u.y = *(uint32_t*)&h1;
        *(uint2*)(g_wq16 + i * 4) = u;
    }
    if (i < Cn * Cn / 4) {
        float4 v = *(const float4*)(pw + i * 4);
        __half2 h0 = __floats2half2_rn(v.x, v.y);
        __half2 h1 = __floats2half2_rn(v.z, v.w);
        uint2 u; u.x = *(uint32_t*)&h0; u.y = *(uint32_t*)&h1;
        *(uint2*)(g_wp16 + i * 4) = u;
    }
}

// ---------------------------------------------------------------------------
// Kernel 1: GroupNorm -> fp16. One block per (batch, group).
// ---------------------------------------------------------------------------
__global__ __launch_bounds__(256) void gn_kernel(
    const float* __restrict__ x, const float* __restrict__ sc,
    const float* __restrict__ bi)
{
    int bg = blockIdx.x;
    int b = bg >> 5;
    int g = bg & 31;
    int base = (b * Cn + g * 16) * Tn;
    const int NELEM = 16 * Tn;

    float s = 0.f, ss = 0.f;
    for (int i = threadIdx.x; i < NELEM / 4; i += 256) {
        float4 v = *(const float4*)(x + base + i * 4);
        s += v.x + v.y + v.z + v.w;
        ss += v.x * v.x + v.y * v.y + v.z * v.z + v.w * v.w;
    }
    #pragma unroll
    for (int o = 16; o; o >>= 1) {
        s  += __shfl_xor_sync(0xffffffffu, s,  o);
        ss += __shfl_xor_sync(0xffffffffu, ss, o);
    }
    __shared__ float rs[8], rss[8], stats[2];
    int warp = threadIdx.x >> 5, lane = threadIdx.x & 31;
    if (lane == 0) { rs[warp] = s; rss[warp] = ss; }
    __syncthreads();
    if (threadIdx.x == 0) {
        float S = 0.f, SS = 0.f;
        #pragma unroll
        for (int w = 0; w < 8; w++) { S += rs[w]; SS += rss[w]; }
        float mean = S / (float)NELEM;
        float var  = SS / (float)NELEM - mean * mean;
        stats[0] = mean;
        stats[1] = rsqrtf(var + 1e-5f);
    }
    __syncthreads();
    float mean = stats[0], inv = stats[1];
    for (int i = threadIdx.x; i < NELEM / 4; i += 256) {
        int c = g * 16 + (i >> 8);      // i*4 >> 10
        float a = inv * sc[c], bb = bi[c] - mean * a;
        float4 v = *(const float4*)(x + base + i * 4);
        __half2 h0 = __floats2half2_rn(v.x * a + bb, v.y * a + bb);
        __half2 h1 = __floats2half2_rn(v.z * a + bb, v.w * a + bb);
        uint2 u; u.x = *(uint32_t*)&h0; u.y = *(uint32_t*)&h1;
        *(uint2*)(g_xn16 + base + i * 4) = u;
    }
}

// ---------------------------------------------------------------------------
// HMMA GEMM mainloop, cp.async 3-stage ring, ONE sync per K-step,
// prefetch issued AFTER compute (off the post-barrier critical path).
// Block tile 128x128, K-step 64. Dynamic smem: 3 x (A 16KB + B 16KB) = 96KB.
// 256 threads = 8 warps (2 m x 4 n), warp tile 64x32.
// ---------------------------------------------------------------------------
__device__ __forceinline__ void hgemm_issue(
    const __half* __restrict__ Ag, const __half* __restrict__ Bg,
    char* slot, int o0, int t0, int c0, int tid)
{
    uint32_t sA = cvta_s(slot);
    uint32_t sB = sA + 16384;
    #pragma unroll
    for (int r = 0; r < 4; r++) {
        int id = tid + r * 256;
        int m = id >> 3, ch = id & 7;
        cpa16(sA + S128s(m * 128 + ch * 16), Ag + (o0 + m) * Cn + c0 + ch * 8);
    }
    #pragma unroll
    for (int r = 0; r < 4; r++) {
        int id = tid + r * 256;
        int k = id >> 4, ch = id & 15;
        cpa16(sB + S256s(k * 256 + ch * 16), Bg + (c0 + k) * Tn + t0 + ch * 8);
    }
}

__device__ __forceinline__ void hgemm_compute(
    char* slot, float (&acc)[4][4][4], int lane, int wm, int wn)
{
    uint32_t sA = cvta_s(slot);
    uint32_t sB = sA + 16384;
    #pragma unroll
    for (int kk = 0; kk < 4; kk++) {
        uint32_t a[4][4];
        #pragma unroll
        for (int am = 0; am < 4; am++) {
            int row = wm * 64 + am * 16 + (lane & 15);
            int colh = kk * 16 + (lane >> 4) * 8;
            ldmA(a[am], sA + S128s(row * 128 + colh * 2));
        }
        uint32_t bfr[2][4];
        int krow = kk * 16 + (lane & 15);
        int noff = (lane >> 4) * 8;
        #pragma unroll
        for (int p = 0; p < 2; p++)
            ldmA_t(bfr[p], sB + S256s(krow * 256 + (wn * 32 + p * 16 + noff) * 2));
        #pragma unroll
        for (int am = 0; am < 4; am++)
            #pragma unroll
            for (int p = 0; p < 2; p++) {
                mma2(acc[am][2 * p],     a[am], bfr[p][0], bfr[p][1]);
                mma2(acc[am][2 * p + 1], a[am], bfr[p][2], bfr[p][3]);
            }
    }
}

__device__ __forceinline__ void hgemm_main(
    const __half* __restrict__ Ag, const __half* __restrict__ Bg,
    char* smem, float (&acc)[4][4][4], int o0, int t0)
{
    int tid = threadIdx.x;
    int lane = tid & 31, warp = tid >> 5;
    int wm = warp >> 2, wn = warp & 3;

    hgemm_issue(Ag, Bg, smem,         o0, t0, 0,  tid); CP_COMMIT();
    hgemm_issue(Ag, Bg, smem + 32768, o0, t0, 64, tid); CP_COMMIT();

    #pragma unroll 1
    for (int s = 0; s < 8; s++) {
        CP_WAIT1();
        __syncthreads();
        hgemm_compute(smem + (s % 3) * 32768, acc, lane, wm, wn);
        // slot (s+2)%3 == (s-1)%3: its readers all passed this iter's barrier
        if (s + 2 < 8)
            hgemm_issue(Ag, Bg, smem + ((s + 2) % 3) * 32768, o0, t0,
                        (s + 2) * 64, tid);
        CP_COMMIT();
    }
}

// ---------------------------------------------------------------------------
// Kernel 2: QKV GEMM (fp16 TC). Epilogue: +bias, cast fp16, scatter q/k/v.
// q is pre-scaled by SC so attention scores come out in exp2 domain.
// ---------------------------------------------------------------------------
__global__ __launch_bounds__(256, 2) void qkv_hgemm(const float* __restrict__ bias)
{
    extern __shared__ char dsm[];
    int t0 = blockIdx.x * 128, o0 = blockIdx.y * 128, b = blockIdx.z;
    float acc[4][4][4] = {};
    hgemm_main(g_wq16, g_xn16 + b * Cn * Tn, dsm, acc, o0, t0);

    int lane = threadIdx.x & 31, warp = threadIdx.x >> 5;
    int wm = warp >> 2, wn = warp & 3;
    int sel = o0 >> 9;   // whole 128-row tile lies in one of q/k/v
    __half* dst = sel == 0 ? g_q : (sel == 1 ? g_k : g_v);
    float mul = sel == 0 ? SCf : 1.0f;
    #pragma unroll
    for (int am = 0; am < 4; am++) {
        #pragma unroll
        for (int hh = 0; hh < 2; hh++) {
            int orow = o0 + wm * 64 + am * 16 + (lane >> 2) + hh * 8;
            float bv = __ldg(&bias[orow]);
            int rem = orow & 511;
            int base = (b * Cn + rem) * Tn + t0 + wn * 32 + (lane & 3) * 2;
            #pragma unroll
            for (int bn = 0; bn < 4; bn++) {
                float x0 = (acc[am][bn][hh * 2 + 0] + bv) * mul;
                float x1 = (acc[am][bn][hh * 2 + 1] + bv) * mul;
                __half2 h = __floats2half2_rn(x0, x1);
                *(__half2*)(dst + base + bn * 8) = h;
            }
        }
    }
}

// ---------------------------------------------------------------------------
// Kernel 4: Proj GEMM (fp16 TC). Epilogue: +bias +residual, fp32 out.
// ---------------------------------------------------------------------------
__global__ __launch_bounds__(256, 2) void proj_hgemm(
    const float* __restrict__ bias, const float* __restrict__ x,
    float* __restrict__ out)
{
    extern __shared__ char dsm[];
    int t0 = blockIdx.x * 128, o0 = blockIdx.y * 128, b = blockIdx.z;
    float acc[4][4][4] = {};
    hgemm_main(g_wp16, g_a16 + b * Cn * Tn, dsm, acc, o0, t0);

    int lane = threadIdx.x & 31, warp = threadIdx.x >> 5;
    int wm = warp >> 2, wn = warp & 3;
    #pragma unroll
    for (int am = 0; am < 4; am++) {
        #pragma unroll
        for (int hh = 0; hh < 2; hh++) {
            int orow = o0 + wm * 64 + am * 16 + (lane >> 2) + hh * 8;
            float bv = __ldg(&bias[orow]);
            int base = (b * Cn + orow) * Tn + t0 + wn * 32 + (lane & 3) * 2;
            #pragma unroll
            for (int bn = 0; bn < 4; bn++) {
                float2 xr = *(const float2*)(x + base + bn * 8);
                float2 o2;
                o2.x = xr.x + acc[am][bn][hh * 2 + 0] + bv;
                o2.y = xr.y + acc[am][bn][hh * 2 + 1] + bv;
                *(float2*)(out + base + bn * 8) = o2;
            }
        }
    }
}

// ---------------------------------------------------------------------------
// Kernel 3: Flash attention (fp16 TC), FAT-WARP (R13 structure) with a
// FOLDED rowsum: the four P A-fragments are summed elementwise in half2
// (independent HADD2s, alu pipe) and ONE all-ones mma per row-set computes
// l — 2 tensor ops/iter instead of 8 on the binding tensor pipe.
// 128 threads = 4 warps; each warp owns 32 query rows (two 16-row A-sets);
// every K/V B-fragment feeds TWO mmas. 3-slot K/V ring, one sync/iter,
// prefetch after compute. Dynamic smem: Q 16KB + 3 x 16KB = 64KB; 2 CTAs/SM.
// ---------------------------------------------------------------------------
__device__ __forceinline__ void issue_kv4(const __half* kb, const __half* vb,
                                          int s0, __half* Ks, int tid)
{
    uint32_t sK = cvta_s(Ks);
    #pragma unroll
    for (int r = 0; r < 4; r++) {
        int id = tid + r * 128;
        int d = id >> 3, ch = id & 7;
        uint32_t off = S128s(d * 128 + ch * 16);
        cpa16(sK + off,        kb + d * Tn + s0 + ch * 8);
        cpa16(sK + 8192 + off, vb + d * Tn + s0 + ch * 8);
    }
}

__global__ __launch_bounds__(128) void attn_h()
{
    extern __shared__ __half smemAll[];       // Q | slot0 | slot1 | slot2
    __half* Qs = smemAll;
    __half* ring = smemAll + 8192;            // 3 slots of 8192 halfs (16KB)

    int t0 = blockIdx.x * 128;
    int bh = blockIdx.z * NHn + blockIdx.y;
    const __half* qb = g_q + bh * Dn * Tn;
    const __half* kb = g_k + bh * Dn * Tn;
    const __half* vb = g_v + bh * Dn * Tn;

    int tid = threadIdx.x, lane = tid & 31, warp = tid >> 5;
    uint32_t sQ = cvta_s(Qs);

    // prologue: async-load K/V tiles 0 and 1 into slots 0 and 1
    issue_kv4(kb, vb, 0, ring, tid);
    CP_COMMIT();
    issue_kv4(kb, vb, 64, ring + 8192, tid);
    CP_COMMIT();

    // load Q tile [d][t0..t0+127] (regular loads, overlap with cp.async)
    #pragma unroll
    for (int r = 0; r < 8; r++) {
        int id = tid + r * 128;
        int d = id >> 4, ch = id & 15;
        uint4 v = *(const uint4*)(qb + d * Tn + t0 + ch * 8);
        *(uint4*)((char*)Qs + S256s(d * 256 + ch * 16)) = v;
    }
    __syncthreads();

    // Q A-frags: warp owns rows [warp*32, warp*32+32): two 16-row sets
    uint32_t qa0[4][4], qa1[4][4];
    {
        int grp = lane >> 3, rr = lane & 7;
        #pragma unroll
        for (int kk = 0; kk < 4; kk++) {
            int drow = kk * 16 + rr + (grp >> 1) * 8;
            int tc0 = warp * 32 + (grp & 1) * 8;
            ldmA_t(qa0[kk], sQ + S256s(drow * 256 + tc0 * 2));
            ldmA_t(qa1[kk], sQ + S256s(drow * 256 + (tc0 + 16) * 2));
        }
    }

    const uint32_t ONE2 = 0x3C003C00u;               // half2(1,1)
    float o0[8][4] = {}, o1[8][4] = {};
    float lC0[4] = {}, lC1[4] = {};

    #pragma unroll 1
    for (int it = 0; it < 16; it++) {
        CP_WAIT1();
        __syncthreads();

        uint32_t sK = cvta_s(ring + (it % 3) * 8192);
        uint32_t sV = sK + 8192;

        // S = Q^T K for both row-sets; each B-frag used twice
        float sf0[8][4], sf1[8][4];
        #pragma unroll
        for (int jn = 0; jn < 8; jn++)
            #pragma unroll
            for (int c = 0; c < 4; c++) { sf0[jn][c] = 0.f; sf1[jn][c] = 0.f; }
        #pragma unroll
        for (int kk = 0; kk < 4; kk++) {
            uint32_t bf[4][4];
            int krow = kk * 16 + (lane & 15);
            int noff = (lane >> 4) * 8;
            #pragma unroll
            for (int p = 0; p < 4; p++)
                ldmA_t(bf[p], sK + S128s(krow * 128 + (p * 16 + noff) * 2));
            #pragma unroll
            for (int p = 0; p < 4; p++) {
                mma2(sf0[2 * p],     qa0[kk], bf[p][0], bf[p][1]);
                mma2(sf0[2 * p + 1], qa0[kk], bf[p][2], bf[p][3]);
                mma2(sf1[2 * p],     qa1[kk], bf[p][0], bf[p][1]);
                mma2(sf1[2 * p + 1], qa1[kk], bf[p][2], bf[p][3]);
            }
        }

        // P = exp2(S): pack + h2exp2; result IS the PV A-fragment layout
        uint32_t pa0[4][4], pa1[4][4];
        #pragma unroll
        for (int jj = 0; jj < 4; jj++) {
            pa0[jj][0] = hexp2pack(sf0[2 * jj][0],     sf0[2 * jj][1]);
            pa0[jj][1] = hexp2pack(sf0[2 * jj][2],     sf0[2 * jj][3]);
            pa0[jj][2] = hexp2pack(sf0[2 * jj + 1][0], sf0[2 * jj + 1][1]);
            pa0[jj][3] = hexp2pack(sf0[2 * jj + 1][2], sf0[2 * jj + 1][3]);
            pa1[jj][0] = hexp2pack(sf1[2 * jj][0],     sf1[2 * jj][1]);
            pa1[jj][1] = hexp2pack(sf1[2 * jj][2],     sf1[2 * jj][3]);
            pa1[jj][2] = hexp2pack(sf1[2 * jj + 1][0], sf1[2 * jj + 1][1]);
            pa1[jj][3] = hexp2pack(sf1[2 * jj + 1][2], sf1[2 * jj + 1][3]);
        }

        // folded rowsum: sum the 4 P fragments elementwise (independent
        // HADD2s on the alu pipe), then ONE all-ones mma per row-set.
        {
            uint32_t ps0[4], ps1[4];
            #pragma unroll
            for (int r = 0; r < 4; r++) {
                ps0[r] = hadd2u(hadd2u(pa0[0][r], pa0[1][r]),
                                hadd2u(pa0[2][r], pa0[3][r]));
                ps1[r] = hadd2u(hadd2u(pa1[0][r], pa1[1][r]),
                                hadd2u(pa1[2][r], pa1[3][r]));
            }
            mma2(lC0, ps0, ONE2, ONE2);
            mma2(lC1, ps1, ONE2, ONE2);
        }

        // O += P V; each V B-frag used twice.
        #pragma unroll
        for (int jj = 0; jj < 4; jj++) {
            uint32_t bf[4][4];
            int scol = jj * 16 + ((lane >> 3) & 1) * 8;
            #pragma unroll
            for (int p = 0; p < 4; p++) {
                int drow = (2 * p + (lane >> 4)) * 8 + (lane & 7);
                ldmA(bf[p], sV + S128s(drow * 128 + scol * 2));
            }
            #pragma unroll
            for (int p = 0; p < 4; p++) {
                mma2(o0[2 * p],     pa0[jj], bf[p][0], bf[p][1]);
                mma2(o0[2 * p + 1], pa0[jj], bf[p][2], bf[p][3]);
                mma2(o1[2 * p],     pa1[jj], bf[p][0], bf[p][1]);
                mma2(o1[2 * p + 1], pa1[jj], bf[p][2], bf[p][3]);
            }
        }

        // prefetch tile it+2 into slot (it+2)%3 == (it-1)%3
        if (it + 2 < 16)
            issue_kv4(kb, vb, it * 64 + 128, ring + ((it + 2) % 3) * 8192, tid);
        CP_COMMIT();
    }

    // epilogue: normalize, stage [d][t] in Q buffer, copy out
    __syncthreads();
    float i00 = 1.f / lC0[0], i01 = 1.f / lC0[2];
    float i10 = 1.f / lC1[0], i11 = 1.f / lC1[2];
    #pragma unroll
    for (int jn = 0; jn < 8; jn++) {
        int d = jn * 8 + (lane & 3) * 2;
        int tl = warp * 32 + (lane >> 2);
        *(__half*)((char*)Qs + S256s( d      * 256 +  tl       * 2)) = __float2half(o0[jn][0] * i00);
        *(__half*)((char*)Qs + S256s((d + 1) * 256 +  tl       * 2)) = __float2half(o0[jn][1] * i00);
        *(__half*)((char*)Qs + S256s( d      * 256 + (tl + 8)  * 2)) = __float2half(o0[jn][2] * i01);
        *(__half*)((char*)Qs + S256s((d + 1) * 256 + (tl + 8)  * 2)) = __float2half(o0[jn][3] * i01);
        *(__half*)((char*)Qs + S256s( d      * 256 + (tl + 16) * 2)) = __float2half(o1[jn][0] * i10);
        *(__half*)((char*)Qs + S256s((d + 1) * 256 + (tl + 16) * 2)) = __float2half(o1[jn][1] * i10);
        *(__half*)((char*)Qs + S256s( d      * 256 + (tl + 24) * 2)) = __float2half(o1[jn][2] * i11);
        *(__half*)((char*)Qs + S256s((d + 1) * 256 + (tl + 24) * 2)) = __float2half(o1[jn][3] * i11);
    }
    __syncthreads();
    #pragma unroll
    for (int r = 0; r < 8; r++) {
        int id = tid + r * 128;
        int d = id >> 4, ch = id & 15;
        uint4 v = *(const uint4*)((char*)Qs + S256s(d * 256 + ch * 16));
        *(uint4*)(g_a16 + (bh * Dn + d) * Tn + t0 + ch * 8) = v;
    }
}

// ---------------------------------------------------------------------------
extern "C" void kernel_launch(void* const* d_in, const int* in_sizes, int n_in,
                              void* d_out, int out_size)
{
    (void)in_sizes; (void)n_in; (void)out_size;
    const float* x        = (const float*)d_in[0];
    const float* gn_scale = (const float*)d_in[1];
    const float* gn_bias  = (const float*)d_in[2];
    const float* qkv_w    = (const float*)d_in[3];
    const float* qkv_b    = (const float*)d_in[4];
    const float* proj_w   = (const float*)d_in[5];
    const float* proj_b   = (const float*)d_in[6];
    float* out = (float*)d_out;

    static bool attr_done = false;
    if (!attr_done) {
        cudaFuncSetAttribute(qkv_hgemm,
            cudaFuncAttributeMaxDynamicSharedMemorySize, 98304);
        cudaFuncSetAttribute(proj_hgemm,
            cudaFuncAttributeMaxDynamicSharedMemorySize, 98304);
        cudaFuncSetAttribute(attn_h,
            cudaFuncAttributeMaxDynamicSharedMemorySize, 65536);
        attr_done = true;
    }

    conv_w<<<(3 * Cn * Cn / 4 + 255) / 256, 256>>>(qkv_w, proj_w);
    gn_kernel<<<Bn * 32, 256>>>(x, gn_scale, gn_bias);
    qkv_hgemm<<<dim3(Tn / 128, (3 * Cn) / 128, Bn), 256, 98304>>>(qkv_b);
    attn_h<<<dim3(Tn / 128, NHn, Bn), 128, 65536>>>();
    proj_hgemm<<<dim3(Tn / 128, Cn / 128, Bn), 256, 98304>>>(proj_b, x, out);
}